// round 13
// baseline (speedup 1.0000x reference)
#include <cuda_runtime.h>
#include <cuda_bf16.h>
#include <math.h>
#include <stdint.h>

#define BATCH 16
#define CH    256
#define NPIX  16384
#define HEADS 8
#define DH    32
#define NMEM  4
#define SCALE_Q 0.5f
#define LN_EPS 1e-5f

// ---------------- helpers ----------------
__device__ __forceinline__ uint32_t smem_u32(const void* p) {
    uint32_t a;
    asm("{ .reg .u64 t; cvta.to.shared.u64 t, %1; cvt.u32.u64 %0, t; }" : "=r"(a) : "l"(p));
    return a;
}
__device__ __forceinline__ void ldsm_x4(uint32_t* r, uint32_t addr) {
    asm volatile("ldmatrix.sync.aligned.m8n8.x4.shared.b16 {%0,%1,%2,%3}, [%4];"
        : "=r"(r[0]), "=r"(r[1]), "=r"(r[2]), "=r"(r[3]) : "r"(addr));
}
__device__ __forceinline__ void ldsm_x2(uint32_t* r, uint32_t addr) {
    asm volatile("ldmatrix.sync.aligned.m8n8.x2.shared.b16 {%0,%1}, [%2];"
        : "=r"(r[0]), "=r"(r[1]) : "r"(addr));
}
__device__ __forceinline__ void mma16816(float* c, const uint32_t* a, const uint32_t* b) {
    asm volatile("mma.sync.aligned.m16n8k16.row.col.f32.bf16.bf16.f32 "
        "{%0,%1,%2,%3}, {%4,%5,%6,%7}, {%8,%9}, {%0,%1,%2,%3};"
        : "+f"(c[0]), "+f"(c[1]), "+f"(c[2]), "+f"(c[3])
        : "r"(a[0]), "r"(a[1]), "r"(a[2]), "r"(a[3]), "r"(b[0]), "r"(b[1]));
}
__device__ __forceinline__ unsigned split_pack(float v) {
    unsigned short h = __bfloat16_as_ushort(__float2bfloat16(v));
    float hf = __bfloat162float(__ushort_as_bfloat16(h));
    unsigned short l = __bfloat16_as_ushort(__float2bfloat16(v - hf));
    return (unsigned)h | ((unsigned)l << 16);
}
#define CP_ASYNC16(dst, src) asm volatile("cp.async.cg.shared.global [%0], [%1], 16;" :: "r"(dst), "l"(src) : "memory")
#define CP_COMMIT()          asm volatile("cp.async.commit_group;" ::: "memory")
#define CP_WAIT(n)           asm volatile("cp.async.wait_group %0;" :: "n"(n) : "memory")

// ---------------- scratch ----------------
__device__ float g_mean[BATCH*CH];
__device__ float g_rstd[BATCH*CH];
__device__ float g_S[BATCH*HEADS*DH*DH];
__device__ float g_Z[BATCH*HEADS*DH];
__device__ unsigned g_whl[768*CH];                 // interleaved (k_out)
__device__ unsigned g_wfhl[BATCH*CH*CH];           // interleaved fused Wf (k_out)
__device__ unsigned short g_wh[512*CH];            // deinterleaved K/V weight hi
__device__ unsigned short g_wl[512*CH];            // deinterleaved K/V weight lo

// ---------------- k_zero ----------------
__global__ void k_zero() {
    int i = blockIdx.x * 256 + threadIdx.x;
    if (i < BATCH*HEADS*DH*DH) g_S[i] = 0.f;
    if (i < BATCH*HEADS*DH)    g_Z[i] = 0.f;
}

// ---------------- k_stats ----------------
__global__ __launch_bounds__(256) void k_stats(const float* __restrict__ x) {
    int bc = blockIdx.x;
    const float4* p = (const float4*)(x + (size_t)bc * NPIX);
    float s = 0.f, ss = 0.f;
    for (int i = threadIdx.x; i < NPIX/4; i += 256) {
        float4 v = p[i];
        s  += v.x + v.y + v.z + v.w;
        ss += v.x*v.x + v.y*v.y + v.z*v.z + v.w*v.w;
    }
    __shared__ float rs[256], rq[256];
    rs[threadIdx.x] = s; rq[threadIdx.x] = ss;
    __syncthreads();
    for (int o = 128; o > 0; o >>= 1) {
        if (threadIdx.x < o) { rs[threadIdx.x] += rs[threadIdx.x+o]; rq[threadIdx.x] += rq[threadIdx.x+o]; }
        __syncthreads();
    }
    if (threadIdx.x == 0) {
        float m   = rs[0] * (1.f / NPIX);
        float var = rq[0] * (1.f / NPIX) - m * m;
        g_mean[bc] = m;
        g_rstd[bc] = rsqrtf(var + LN_EPS);
    }
}

// ---------------- k_wprep: interleaved (q rows) + deinterleaved (kv rows) ----------
__global__ void k_wprep(const float* __restrict__ w_qkv) {
    int i = blockIdx.x * 256 + threadIdx.x;
    unsigned pk = split_pack(w_qkv[i]);
    g_whl[i] = pk;
    if (i >= 256*CH) {
        int r = i - 256*CH;
        g_wh[r] = (unsigned short)pk;
        g_wl[r] = (unsigned short)(pk >> 16);
    }
}

// ---------------- k_kv_mma: 64-px tile, cp.async double-buffered weights ----------
// smem: XB_HI [64px][264] @0 (33792), XB_LO @33792
//       A buffers @67584: buf{0,1} x (hi,lo) [512 rows][40 elem] (40960 each)
//       epilogue alias: EK_HI 0 / EK_LO 36864 / V_HI 73728 / V_LO 110592 ([256][72])
#define SA2 40
#define XBH 0
#define XBL 33792
#define AB  67584
#define ABUF 81920
#define KV_SMEM 231424
#define SV 72
#define EK_HI 0
#define EK_LO 36864
#define V_HI  73728
#define V_LO  110592
#define SX 264

__global__ __launch_bounds__(512, 1) void k_kv_mma(const float* __restrict__ x) {
    extern __shared__ char dsm[];
    const int b = blockIdx.y, pt = blockIdx.x;
    const int t = threadIdx.x, lane = t & 31, w = t >> 5;
    const uint32_t smb = smem_u32(dsm);

    const float* xb = x + (size_t)b * CH * NPIX + (size_t)pt * 64;

    const int lrow = lane & 7, seg = lane >> 3;
    const int aoffA = ((seg & 1) * 8 + lrow) * SA2 + (seg >> 1) * 8;
    const int l2 = lane & 15;
    const int boffx = (l2 & 7) * SX + (l2 >> 3) * 8;
    const int gid = lane >> 2, tig = lane & 3;

    const int rw = w & 7;        // 64-row slice
    const int ph = w >> 3;       // px half
    const int pb = ph * 32;

    // ---- cp.async chunk issue: 32 ch, hi+lo tiles, 8 x 16B per thread ----
    #define ISSUE_CHUNK(c, buf) do { \
        const int _c0 = (c) * 32; \
        const uint32_t _base = smb + AB + (buf) * ABUF; \
        _Pragma("unroll") \
        for (int _i = 0; _i < 8; _i++) { \
            int _flat = t + _i * 512; \
            int _r = _flat >> 3, _rem = _flat & 7; \
            int _tl = _rem >> 2, _sg = _rem & 3; \
            const unsigned short* _src = (_tl ? g_wl : g_wh) + (size_t)_r * CH + _c0 + _sg * 8; \
            uint32_t _dst = _base + _tl * 40960 + _r * (SA2*2) + _sg * 16; \
            CP_ASYNC16(_dst, _src); \
        } \
        CP_COMMIT(); \
    } while (0)

    ISSUE_CHUNK(0, 0);
    ISSUE_CHUNK(1, 1);

    // ---- pack xn full-K as split-bf16 XB[px][264] (overlaps with cp.async) ----
    #pragma unroll
    for (int i = 0; i < 8; i++) {
        int flat = t + i * 512;
        int ch = flat >> 4, pxq = (flat & 15) * 4;
        float4 v4 = *(const float4*)(xb + (size_t)ch * NPIX + pxq);
        float m = g_mean[b*CH + ch], r = g_rstd[b*CH + ch];
        float vals[4] = {(v4.x-m)*r, (v4.y-m)*r, (v4.z-m)*r, (v4.w-m)*r};
        #pragma unroll
        for (int j = 0; j < 4; j++) {
            unsigned pk = split_pack(vals[j]);
            uint32_t off = (uint32_t)((pxq + j) * SX + ch) * 2;
            *(unsigned short*)(dsm + XBH + off) = (unsigned short)pk;
            *(unsigned short*)(dsm + XBL + off) = (unsigned short)(pk >> 16);
        }
    }

    float acc[4][4][4];
    #pragma unroll
    for (int m = 0; m < 4; m++)
        #pragma unroll
        for (int n = 0; n < 4; n++)
            #pragma unroll
            for (int q = 0; q < 4; q++) acc[m][n][q] = 0.f;

    #pragma unroll 1
    for (int c = 0; c < 8; c++) {
        if (c < 7) { CP_WAIT(1); } else { CP_WAIT(0); }
        __syncthreads();
        const uint32_t abase = smb + AB + (c & 1) * ABUF;

        #pragma unroll
        for (int ks = 0; ks < 2; ks++) {
            const int kg = c * 32 + ks * 16;   // global ch offset (B side)
            const int k0 = ks * 16;            // within-chunk offset (A side)
            uint32_t bh[4][2], bl[4][2];
            #pragma unroll
            for (int n = 0; n < 4; n++) {
                uint32_t bo = (uint32_t)((pb + n * 8) * SX + kg + boffx) * 2;
                ldsm_x2(bh[n], smb + XBH + bo);
                ldsm_x2(bl[n], smb + XBL + bo);
            }
            #pragma unroll
            for (int m = 0; m < 4; m++) {
                uint32_t ah[4], al[4];
                uint32_t ao = (uint32_t)((rw * 64 + m * 16) * SA2 + k0 + aoffA) * 2;
                ldsm_x4(ah, abase + ao);
                ldsm_x4(al, abase + 40960 + ao);
                #pragma unroll
                for (int n = 0; n < 4; n++) {
                    mma16816(acc[m][n], ah, bh[n]);
                    mma16816(acc[m][n], ah, bl[n]);
                    mma16816(acc[m][n], al, bh[n]);
                }
            }
        }
        __syncthreads();
        if (c + 2 < 8) ISSUE_CHUNK(c + 2, c & 1);
    }

    // ---- epilogue stage 1: exp/pack K (+Z), pack V into [256][SV] split tiles ----
    if (rw < 4) {
        #pragma unroll
        for (int m = 0; m < 4; m++) {
            int row = rw * 64 + m * 16 + gid;
            float zr = 0.f, zr8 = 0.f;
            #pragma unroll
            for (int n = 0; n < 4; n++) {
                int px = pb + n * 8 + 2 * tig;
                float e0 = expf(acc[m][n][0]);
                float e1 = expf(acc[m][n][1]);
                float e2 = expf(acc[m][n][2]);
                float e3 = expf(acc[m][n][3]);
                zr  += e0 + e1;
                zr8 += e2 + e3;
                unsigned p0 = split_pack(e0), p1 = split_pack(e1);
                unsigned p2 = split_pack(e2), p3 = split_pack(e3);
                *(unsigned*)(dsm + EK_HI + ( row      * SV + px) * 2) = __byte_perm(p0, p1, 0x5410);
                *(unsigned*)(dsm + EK_LO + ( row      * SV + px) * 2) = __byte_perm(p0, p1, 0x7632);
                *(unsigned*)(dsm + EK_HI + ((row + 8) * SV + px) * 2) = __byte_perm(p2, p3, 0x5410);
                *(unsigned*)(dsm + EK_LO + ((row + 8) * SV + px) * 2) = __byte_perm(p2, p3, 0x7632);
            }
            zr  += __shfl_xor_sync(0xFFFFFFFFu, zr, 1);
            zr  += __shfl_xor_sync(0xFFFFFFFFu, zr, 2);
            zr8 += __shfl_xor_sync(0xFFFFFFFFu, zr8, 1);
            zr8 += __shfl_xor_sync(0xFFFFFFFFu, zr8, 2);
            if (tig == 0) {
                atomicAdd(&g_Z[b*256 + row],     zr);
                atomicAdd(&g_Z[b*256 + row + 8], zr8);
            }
        }
    } else {
        #pragma unroll
        for (int m = 0; m < 4; m++) {
            int vr = (rw - 4) * 64 + m * 16 + gid;
            #pragma unroll
            for (int n = 0; n < 4; n++) {
                int px = pb + n * 8 + 2 * tig;
                unsigned p0 = split_pack(acc[m][n][0]), p1 = split_pack(acc[m][n][1]);
                unsigned p2 = split_pack(acc[m][n][2]), p3 = split_pack(acc[m][n][3]);
                *(unsigned*)(dsm + V_HI + ( vr      * SV + px) * 2) = __byte_perm(p0, p1, 0x5410);
                *(unsigned*)(dsm + V_LO + ( vr      * SV + px) * 2) = __byte_perm(p0, p1, 0x7632);
                *(unsigned*)(dsm + V_HI + ((vr + 8) * SV + px) * 2) = __byte_perm(p2, p3, 0x5410);
                *(unsigned*)(dsm + V_LO + ((vr + 8) * SV + px) * 2) = __byte_perm(p2, p3, 0x7632);
            }
        }
    }
    __syncthreads();

    // ---- epilogue stage 2: S = ek · v^T via MMA; 2 warps per head (K=32 each) ----
    {
        const int h  = w & 7;
        const int kb = (w >> 3) * 32;
        const int aoff2 = ((seg & 1) * 8 + lrow) * SV + (seg >> 1) * 8;
        const int boff2 = (l2 & 7) * SV + (l2 >> 3) * 8;
        float sc[2][4][4];
        #pragma unroll
        for (int m = 0; m < 2; m++)
            #pragma unroll
            for (int n = 0; n < 4; n++)
                #pragma unroll
                for (int q = 0; q < 4; q++) sc[m][n][q] = 0.f;

        #pragma unroll
        for (int kk = 0; kk < 2; kk++) {
            const int k0 = kb + kk * 16;
            uint32_t bh2[4][2], bl2[4][2];
            #pragma unroll
            for (int n = 0; n < 4; n++) {
                uint32_t bo = (uint32_t)((h*32 + n*8) * SV + k0 + boff2) * 2;
                ldsm_x2(bh2[n], smb + V_HI + bo);
                ldsm_x2(bl2[n], smb + V_LO + bo);
            }
            #pragma unroll
            for (int m = 0; m < 2; m++) {
                uint32_t ah[4], al[4];
                uint32_t ao = (uint32_t)((h*32 + m*16) * SV + k0 + aoff2) * 2;
                ldsm_x4(ah, smb + EK_HI + ao);
                ldsm_x4(al, smb + EK_LO + ao);
                #pragma unroll
                for (int n = 0; n < 4; n++) {
                    mma16816(sc[m][n], ah, bh2[n]);
                    mma16816(sc[m][n], ah, bl2[n]);
                    mma16816(sc[m][n], al, bh2[n]);
                }
            }
        }
        float* Sb = g_S + (size_t)(b*HEADS + h) * (DH*DH);
        #pragma unroll
        for (int m = 0; m < 2; m++) {
            int d = m*16 + gid;
            #pragma unroll
            for (int n = 0; n < 4; n++) {
                int e = n*8 + 2*tig;
                atomicAdd(&Sb[ d      * DH + e    ], sc[m][n][0]);
                atomicAdd(&Sb[ d      * DH + e + 1], sc[m][n][1]);
                atomicAdd(&Sb[(d + 8) * DH + e    ], sc[m][n][2]);
                atomicAdd(&Sb[(d + 8) * DH + e + 1], sc[m][n][3]);
            }
        }
    }
}

// ---------------- k_wf: finalize ctx, fold into W_out, write split-packed -----------
__global__ __launch_bounds__(256) void k_wf(const float* __restrict__ mem_kv,
                                            const float* __restrict__ w_out) {
    __shared__ float ctxsm[DH*DH];
    __shared__ float wsm[CH*33];
    const int h = blockIdx.x, b = blockIdx.y;
    const int t = threadIdx.x;
    {
        int d  = t >> 3;
        int e0 = (t & 7) * 4;
        float ekm[NMEM];
        float zm = 0.f;
        #pragma unroll
        for (int m = 0; m < NMEM; m++) {
            ekm[m] = expf(mem_kv[(h*DH + d)*NMEM + m]);
            zm += ekm[m];
        }
        float inv = 1.f / (g_Z[(b*HEADS + h)*DH + d] + zm);
        #pragma unroll
        for (int j = 0; j < 4; j++) {
            int e = e0 + j;
            float s = g_S[((size_t)(b*HEADS + h)*DH + d)*DH + e];
            float sm = 0.f;
            #pragma unroll
            for (int m = 0; m < NMEM; m++)
                sm = fmaf(ekm[m], mem_kv[HEADS*DH*NMEM + (h*DH + e)*NMEM + m], sm);
            ctxsm[d*DH + e] = (s + sm) * inv;
        }
    }
    #pragma unroll
    for (int i = 0; i < 8; i++) {
        int idx = t + i * 256;
        int c = idx >> 3, eq = (idx & 7) * 4;
        float4 wv = *(const float4*)(w_out + (size_t)c * CH + h*DH + eq);
        wsm[c*33 + eq+0] = wv.x; wsm[c*33 + eq+1] = wv.y;
        wsm[c*33 + eq+2] = wv.z; wsm[c*33 + eq+3] = wv.w;
    }
    __syncthreads();
    float acc[DH];
    #pragma unroll
    for (int d = 0; d < DH; d++) acc[d] = 0.f;
    for (int e = 0; e < DH; e++) {
        float wv = wsm[t*33 + e];
        #pragma unroll
        for (int d = 0; d < DH; d++)
            acc[d] = fmaf(wv, ctxsm[d*DH + e], acc[d]);
    }
    unsigned* dst = g_wfhl + ((size_t)b*CH + t)*CH + h*DH;
    #pragma unroll
    for (int d = 0; d < DH; d++) dst[d] = split_pack(acc[d]);
}

// ---------------- k_out_mma: 64-px tile, 512 threads (unchanged from R12) ----------
#define SAO 72
#define OXH 0
#define OXL 33792
#define OAH 67584
#define OAL 104448
#define OQ  141312
#define OQH 141312
#define OQL 175104
#define OUT_SMEM 215040

__global__ __launch_bounds__(512, 1) void k_out_mma(const float* __restrict__ x,
                                                    const float* __restrict__ b_out,
                                                    const float* __restrict__ ln_g,
                                                    float* __restrict__ out) {
    extern __shared__ char dsm[];
    __shared__ float colsum[8][64], colsq[8][64], mcol[64], rcol[64];
    const int b = blockIdx.y, pt = blockIdx.x;
    const int t = threadIdx.x, lane = t & 31, w = t >> 5;
    const uint32_t smb = smem_u32(dsm);
    float* Q = (float*)(dsm + OQ);

    const float* xb = x + (size_t)b * CH * NPIX + (size_t)pt * 64;

    #pragma unroll
    for (int i = 0; i < 8; i++) {
        int flat = t + i * 512;
        int ch = flat >> 4, pxq = (flat & 15) * 4;
        float4 v4 = *(const float4*)(xb + (size_t)ch * NPIX + pxq);
        float m = g_mean[b*CH + ch], r = g_rstd[b*CH + ch];
        float vals[4] = {(v4.x-m)*r, (v4.y-m)*r, (v4.z-m)*r, (v4.w-m)*r};
        #pragma unroll
        for (int j = 0; j < 4; j++) {
            unsigned pk = split_pack(vals[j]);
            uint32_t off = (uint32_t)((pxq + j) * SX + ch) * 2;
            *(unsigned short*)(dsm + OXH + off) = (unsigned short)pk;
            *(unsigned short*)(dsm + OXL + off) = (unsigned short)(pk >> 16);
        }
    }
    __syncthreads();

    const int lrow = lane & 7, seg = lane >> 3;
    const int aoff = ((seg & 1) * 8 + lrow) * SAO + (seg >> 1) * 8;
    const int l2 = lane & 15;
    const int boffx = (l2 & 7) * SX + (l2 >> 3) * 8;
    const int gid = lane >> 2, tig = lane & 3;

    const int rw = w & 7;
    const int ph = w >> 3;
    const int pb = ph * 32;

    const uint4* wq4 = (const uint4*)g_whl;
    const uint4* wf4 = (const uint4*)(g_wfhl + (size_t)b * CH * CH);

    float acc[2][4][4];

    #pragma unroll 1
    for (int pass = 0; pass < 2; pass++) {
        const uint4* wsrc = pass ? wf4 : wq4;
        const uint32_t bhb = pass ? OQH : OXH;
        const uint32_t blb = pass ? OQL : OXL;
        #pragma unroll
        for (int m = 0; m < 2; m++)
            #pragma unroll
            for (int n = 0; n < 4; n++)
                #pragma unroll
                for (int q = 0; q < 4; q++) acc[m][n][q] = 0.f;

        #pragma unroll 1
        for (int c = 0; c < 4; c++) {
            #pragma unroll
            for (int i = 0; i < 8; i++) {
                int flat = t + i * 512;
                int r = flat >> 4, q = flat & 15;
                uint4 u = wsrc[(size_t)r * 64 + c * 16 + q];
                uint32_t off = (uint32_t)r * (SAO*2) + q * 8;
                *(uint2*)(dsm + OAH + off) = make_uint2(__byte_perm(u.x,u.y,0x5410), __byte_perm(u.z,u.w,0x5410));
                *(uint2*)(dsm + OAL + off) = make_uint2(__byte_perm(u.x,u.y,0x7632), __byte_perm(u.z,u.w,0x7632));
            }
            __syncthreads();

            #pragma unroll
            for (int ks = 0; ks < 4; ks++) {
                const int k0 = c * 64 + ks * 16;
                uint32_t bh[4][2], bl[4][2];
                #pragma unroll
                for (int n = 0; n < 4; n++) {
                    uint32_t bo = (uint32_t)((pb + n * 8) * SX + k0 + boffx) * 2;
                    ldsm_x2(bh[n], smb + bhb + bo);
                    ldsm_x2(bl[n], smb + blb + bo);
                }
                #pragma unroll
                for (int m = 0; m < 2; m++) {
                    uint32_t ah[4], al[4];
                    uint32_t ao = (uint32_t)((rw * 32 + m * 16) * SAO + ks * 16 + aoff) * 2;
                    ldsm_x4(ah, smb + OAH + ao);
                    ldsm_x4(al, smb + OAL + ao);
                    #pragma unroll
                    for (int n = 0; n < 4; n++) {
                        mma16816(acc[m][n], ah, bh[n]);
                        mma16816(acc[m][n], ah, bl[n]);
                        mma16816(acc[m][n], al, bh[n]);
                    }
                }
            }
            __syncthreads();
        }

        if (pass == 0) {
            #pragma unroll
            for (int m = 0; m < 2; m++) {
                int row = rw * 32 + m * 16 + gid;
                #pragma unroll
                for (int n = 0; n < 4; n++) {
                    int px = pb + n * 8 + 2 * tig;
                    Q[ row      * 72 + px    ] = acc[m][n][0];
                    Q[ row      * 72 + px + 1] = acc[m][n][1];
                    Q[(row + 8) * 72 + px    ] = acc[m][n][2];
                    Q[(row + 8) * 72 + px + 1] = acc[m][n][3];
                }
            }
            __syncthreads();
            {
                const int h = t >> 6, p = t & 63;
                float vals[32];
                float mx = -1e30f;
                #pragma unroll
                for (int dd = 0; dd < 32; dd++) {
                    vals[dd] = Q[(h*32 + dd) * 72 + p];
                    mx = fmaxf(mx, vals[dd]);
                }
                float s = 0.f;
                #pragma unroll
                for (int dd = 0; dd < 32; dd++) { vals[dd] = expf(vals[dd] - mx); s += vals[dd]; }
                float inv = SCALE_Q / s;
                __syncthreads();
                #pragma unroll
                for (int dd = 0; dd < 32; dd++) {
                    unsigned pk = split_pack(vals[dd] * inv);
                    uint32_t off = (uint32_t)(p * SX + h*32 + dd) * 2;
                    *(unsigned short*)(dsm + OQH + off) = (unsigned short)pk;
                    *(unsigned short*)(dsm + OQL + off) = (unsigned short)(pk >> 16);
                }
            }
            __syncthreads();
        }
    }

    #pragma unroll
    for (int m = 0; m < 2; m++) {
        int row = rw * 32 + m * 16 + gid;
        float bo0 = b_out[row], bo8 = b_out[row + 8];
        #pragma unroll
        for (int n = 0; n < 4; n++) {
            int px = pb + n * 8 + 2 * tig;
            Q[ row      * 72 + px    ] = acc[m][n][0] + bo0;
            Q[ row      * 72 + px + 1] = acc[m][n][1] + bo0;
            Q[(row + 8) * 72 + px    ] = acc[m][n][2] + bo8;
            Q[(row + 8) * 72 + px + 1] = acc[m][n][3] + bo8;
        }
    }
    __syncthreads();

    const int cb = t >> 6, p = t & 63;
    {
        float ps = 0.f, pq = 0.f;
        #pragma unroll 4
        for (int i = 0; i < 32; i++) {
            float v = Q[(cb + i * 8) * 72 + p];
            ps += v; pq += v * v;
        }
        colsum[cb][p] = ps; colsq[cb][p] = pq;
    }
    __syncthreads();
    if (t < 64) {
        float s = 0.f, q2 = 0.f;
        #pragma unroll
        for (int sg = 0; sg < 8; sg++) { s += colsum[sg][t]; q2 += colsq[sg][t]; }
        float m   = s * (1.f / 256.f);
        float var = q2 * (1.f / 256.f) - m * m;
        mcol[t] = m;
        rcol[t] = rsqrtf(var + LN_EPS);
    }
    __syncthreads();
    float* ob = out + (size_t)b * CH * NPIX + (size_t)pt * 64;
    #pragma unroll 4
    for (int i = 0; i < 32; i++) {
        int c = cb + i * 8;
        uint32_t off = (uint32_t)(p * SX + c) * 2;
        float xh = __bfloat162float(*(__nv_bfloat16*)(dsm + OXH + off));
        float xl = __bfloat162float(*(__nv_bfloat16*)(dsm + OXL + off));
        float v = (Q[c*72 + p] - mcol[p]) * rcol[p] * ln_g[c] + (xh + xl);
        ob[(size_t)c * NPIX + p] = v;
    }
}

// ---------------- launch ----------------
extern "C" void kernel_launch(void* const* d_in, const int* in_sizes, int n_in,
                              void* d_out, int out_size) {
    const float* x      = (const float*)d_in[0];
    const float* w_qkv  = (const float*)d_in[1];
    const float* mem_kv = (const float*)d_in[2];
    const float* w_out  = (const float*)d_in[3];
    const float* b_out  = (const float*)d_in[4];
    const float* ln_g   = (const float*)d_in[5];
    float* out = (float*)d_out;

    cudaFuncSetAttribute(k_kv_mma,  cudaFuncAttributeMaxDynamicSharedMemorySize, KV_SMEM);
    cudaFuncSetAttribute(k_out_mma, cudaFuncAttributeMaxDynamicSharedMemorySize, OUT_SMEM);

    k_zero<<<512, 256>>>();
    k_stats<<<BATCH * CH, 256>>>(x);
    k_wprep<<<768, 256>>>(w_qkv);
    k_kv_mma<<<dim3(NPIX/64, BATCH), 512, KV_SMEM>>>(x);
    k_wf<<<dim3(HEADS, BATCH), 256>>>(mem_kv, w_out);
    k_out_mma<<<dim3(NPIX/64, BATCH), 512, OUT_SMEM>>>(x, b_out, ln_g, out);
}